// round 4
// baseline (speedup 1.0000x reference)
#include <cuda_runtime.h>
#include <math.h>

#define BB 64
#define MM 512
#define SS 1024
#define EE 128
#define CC 10000
#define MSPLIT 8
#define NSPLIT 16
#define KCHUNK (SS / NSPLIT)  /* 64 */
#define BLK5 ((CC + 63) / 64) /* 157 */
#define PREF 8

// ---------------- scratch (device globals; no allocation) ----------------
__device__ __align__(16) float g_partial[BB * MSPLIT * SS];   // 2 MB
__device__ __align__(16) float g_gpart[2 * NSPLIT * BB * EE]; // 1 MB
__device__ __align__(16) float g_u[BB * EE];                  // 32 KB
__device__ __align__(16) float g_logits[BB * CC];             // 2.56 MB (exp(logits))
__device__ __align__(16) float g_psum[BB * BLK5];
__device__ __align__(16) float g_dummy[64 * 256];

// ---------------- kernel 1: reduce stories over M + prefetch weights ------------
__global__ void k1_reduce_stories(const float* __restrict__ stories,
                                  const float* __restrict__ queries,
                                  const float* __restrict__ W1,
                                  const float* __restrict__ W2,
                                  const float* __restrict__ W3) {
    int blk = blockIdx.x;
    int t = threadIdx.x;

    if (blk >= BB * MSPLIT) {  // ---- L2 prefetch blocks ----
        int lane = (blk - BB * MSPLIT) * 256 + t;
        float s = 0.f;
        const float4* a = (const float4*)W1;
        for (int i = lane; i < 32768; i += PREF * 256) {
            float4 v = __ldcg(&a[i]); s += v.x + v.y + v.z + v.w;
        }
        a = (const float4*)W2;
        for (int i = lane; i < 32768; i += PREF * 256) {
            float4 v = __ldcg(&a[i]); s += v.x + v.y + v.z + v.w;
        }
        a = (const float4*)queries;
        for (int i = lane; i < 16384; i += PREF * 256) {
            float4 v = __ldcg(&a[i]); s += v.x + v.y + v.z + v.w;
        }
        a = (const float4*)W3;
        for (int i = lane; i < 4096; i += PREF * 256) {
            float4 v = __ldcg(&a[i]); s += v.x + v.y + v.z + v.w;
        }
        g_dummy[lane] = s;
        return;
    }

    int b = blk / MSPLIT, ms = blk % MSPLIT;
    const float4* src =
        (const float4*)(stories + (size_t)(b * MM + ms * (MM / MSPLIT)) * SS);
    float4 a0 = make_float4(0.f, 0.f, 0.f, 0.f);
    float4 a1 = a0, a2 = a0, a3 = a0;
#pragma unroll 4
    for (int m = 0; m < MM / MSPLIT; m += 4) {
        float4 v0 = __ldcs(&src[(size_t)(m + 0) * (SS / 4) + t]);
        float4 v1 = __ldcs(&src[(size_t)(m + 1) * (SS / 4) + t]);
        float4 v2 = __ldcs(&src[(size_t)(m + 2) * (SS / 4) + t]);
        float4 v3 = __ldcs(&src[(size_t)(m + 3) * (SS / 4) + t]);
        a0.x += v0.x; a0.y += v0.y; a0.z += v0.z; a0.w += v0.w;
        a1.x += v1.x; a1.y += v1.y; a1.z += v1.z; a1.w += v1.w;
        a2.x += v2.x; a2.y += v2.y; a2.z += v2.z; a2.w += v2.w;
        a3.x += v3.x; a3.y += v3.y; a3.z += v3.z; a3.w += v3.w;
    }
    float4 r;
    r.x = (a0.x + a1.x) + (a2.x + a3.x);
    r.y = (a0.y + a1.y) + (a2.y + a3.y);
    r.z = (a0.z + a1.z) + (a2.z + a3.z);
    r.w = (a0.w + a1.w) + (a2.w + a3.w);
    ((float4*)g_partial)[(size_t)blk * (SS / 4) + t] = r;
}

// ---------------- kernel 3: u0 = queries@W1^T, o = ssum@W2^T (split-K) ----------
__global__ void k3_gemm64(const float* __restrict__ queries,
                          const float* __restrict__ W1,
                          const float* __restrict__ W2,
                          const float* __restrict__ W4) {
    int ks = blockIdx.x;
    int eh = blockIdx.y;
    int which = blockIdx.z;
    const float* W = which ? W2 : W1;
    int kbase = ks * KCHUNK;

    // W4 L2 prefetch for k5
    int bid = ks + NSPLIT * eh + NSPLIT * 2 * which;
    int plane = bid * 256 + threadIdx.x;
    float ps = 0.f;
    const float4* w4 = (const float4*)W4;
    for (int i = plane; i < 320000; i += 64 * 256) {
        float4 v = __ldcg(&w4[i]); ps += v.x + v.y + v.z + v.w;
    }

    __shared__ __align__(16) float Xs[32][68];
    __shared__ __align__(16) float Ws[32][68];

    int tid = threadIdx.x;
    int tb = tid & 15, te = tid >> 4;
    int lrow = tid >> 3, lkq = tid & 7;

    float acc[16];
#pragma unroll
    for (int i = 0; i < 16; i++) acc[i] = 0.f;

    for (int kt = 0; kt < KCHUNK; kt += 32) {
#pragma unroll
        for (int h = 0; h < 2; h++) {
            int row = lrow + 32 * h;
            float4 xv;
            if (which == 0) {
                xv = *(const float4*)&queries[(size_t)row * SS + kbase + kt + lkq * 4];
            } else {
                xv = make_float4(0.f, 0.f, 0.f, 0.f);
#pragma unroll
                for (int msp = 0; msp < MSPLIT; msp++) {
                    float4 v = *(const float4*)&g_partial[
                        (size_t)(row * MSPLIT + msp) * SS + kbase + kt + lkq * 4];
                    xv.x += v.x; xv.y += v.y; xv.z += v.z; xv.w += v.w;
                }
            }
            float4 wv = *(const float4*)&W[(size_t)(eh * 64 + row) * SS + kbase + kt + lkq * 4];
            Xs[lkq * 4 + 0][row] = xv.x; Xs[lkq * 4 + 1][row] = xv.y;
            Xs[lkq * 4 + 2][row] = xv.z; Xs[lkq * 4 + 3][row] = xv.w;
            Ws[lkq * 4 + 0][row] = wv.x; Ws[lkq * 4 + 1][row] = wv.y;
            Ws[lkq * 4 + 2][row] = wv.z; Ws[lkq * 4 + 3][row] = wv.w;
        }
        __syncthreads();
#pragma unroll
        for (int k = 0; k < 32; k++) {
            float4 xv = *(const float4*)&Xs[k][tb * 4];
            float4 wv = *(const float4*)&Ws[k][te * 4];
            acc[0]  += xv.x * wv.x; acc[1]  += xv.x * wv.y;
            acc[2]  += xv.x * wv.z; acc[3]  += xv.x * wv.w;
            acc[4]  += xv.y * wv.x; acc[5]  += xv.y * wv.y;
            acc[6]  += xv.y * wv.z; acc[7]  += xv.y * wv.w;
            acc[8]  += xv.z * wv.x; acc[9]  += xv.z * wv.y;
            acc[10] += xv.z * wv.z; acc[11] += xv.z * wv.w;
            acc[12] += xv.w * wv.x; acc[13] += xv.w * wv.y;
            acc[14] += xv.w * wv.z; acc[15] += xv.w * wv.w;
        }
        __syncthreads();
    }
#pragma unroll
    for (int i = 0; i < 4; i++)
#pragma unroll
        for (int j = 0; j < 4; j++)
            g_gpart[(size_t)((which * NSPLIT + ks) * BB + tb * 4 + i) * EE +
                    eh * 64 + te * 4 + j] = acc[i * 4 + j];
    g_dummy[plane] = ps;
}

// ---------------- kernel 4: split-K combine + 3 hops + L2 normalize -------------
__global__ void k4_hops(const float* __restrict__ W3) {
    __shared__ float us[EE];
    __shared__ float red[4];
    int b = blockIdx.x;
    int f = threadIdx.x;

    float4 w[32];
    const float4* wrow = (const float4*)(W3 + (size_t)f * EE);
#pragma unroll
    for (int q = 0; q < 32; q++) w[q] = __ldcg(&wrow[q]);

    float u = 0.f, o = 0.f;
#pragma unroll
    for (int ks = 0; ks < NSPLIT; ks++) {
        u += g_gpart[(size_t)(ks * BB + b) * EE + f];
        o += g_gpart[(size_t)((NSPLIT + ks) * BB + b) * EE + f];
    }
    us[f] = u;
    __syncthreads();

    float vout = 0.f;
    const float4* us4 = (const float4*)us;
    for (int hop = 0; hop < 3; hop++) {
        float v0 = 0.f, v1 = 0.f, v2 = 0.f, v3 = 0.f;
#pragma unroll
        for (int q = 0; q < 32; q++) {
            float4 uu = us4[q];
            v0 += w[q].x * uu.x;
            v1 += w[q].y * uu.y;
            v2 += w[q].z * uu.z;
            v3 += w[q].w * uu.w;
        }
        float v = o + ((v0 + v1) + (v2 + v3));
        float s = v * v;
#pragma unroll
        for (int off = 16; off; off >>= 1)
            s += __shfl_xor_sync(0xffffffffu, s, off);
        if ((f & 31) == 0) red[f >> 5] = s;
        __syncthreads();
        float tot = (red[0] + red[1]) + (red[2] + red[3]);
        float nrm = fmaxf(sqrtf(tot), 1e-12f);
        vout = v / nrm;
        us[f] = vout;
        __syncthreads();
    }
    g_u[(size_t)b * EE + f] = vout;
}

// ---------------- kernel 5: exp(u @ W4^T) — full-tile preload, barrier-free loop
// grid = 157, block = 512. Tile = [64b x 64c], K = 128 fully staged in shared:
// Xs[k][b] (34.8 KB) + Ws[k][c] (34.8 KB) dynamic. Thread tile 4b x 2c.
// One __syncthreads after load; 128-deep FMA loop with zero barriers.
#define K5PAD 68
__global__ void k5_logits(const float* __restrict__ W4) {
    extern __shared__ float sm[];
    float* Xs = sm;                    // [128][68]
    float* Ws = sm + 128 * K5PAD;      // [128][68]
    float* rpart = sm + 2 * 128 * K5PAD; // [32][65]

    int c0 = blockIdx.x * 64;
    int tid = threadIdx.x;
    int tc = tid & 31;       // column pair: cols tc*2, tc*2+1
    int tbq = tid >> 5;      // 0..15: rows tbq*4 .. +3

    // ---- load phase: transpose g_u and W4 tile into [k][row] layout ----
    {
        int r = tid & 63;          // b or c within tile
        int qb = tid >> 6;         // 0..7
        const float4* usrc = (const float4*)(g_u + (size_t)r * EE);
        int crow = c0 + r;
        const float4* wsrc = (const float4*)(W4 + (size_t)crow * EE);
#pragma unroll
        for (int j = 0; j < 4; j++) {
            int q = qb + 8 * j;    // k-quad 0..31
            float4 xv = usrc[q];
            Xs[(4 * q + 0) * K5PAD + r] = xv.x;
            Xs[(4 * q + 1) * K5PAD + r] = xv.y;
            Xs[(4 * q + 2) * K5PAD + r] = xv.z;
            Xs[(4 * q + 3) * K5PAD + r] = xv.w;
            float4 wv = make_float4(0.f, 0.f, 0.f, 0.f);
            if (crow < CC) wv = wsrc[q];
            Ws[(4 * q + 0) * K5PAD + r] = wv.x;
            Ws[(4 * q + 1) * K5PAD + r] = wv.y;
            Ws[(4 * q + 2) * K5PAD + r] = wv.z;
            Ws[(4 * q + 3) * K5PAD + r] = wv.w;
        }
    }
    __syncthreads();

    // ---- compute: no barriers, X read is warp-broadcast ----
    float a00 = 0.f, a01 = 0.f, a10 = 0.f, a11 = 0.f;
    float a20 = 0.f, a21 = 0.f, a30 = 0.f, a31 = 0.f;
#pragma unroll 8
    for (int k = 0; k < EE; k++) {
        float4 xv = *(const float4*)&Xs[k * K5PAD + tbq * 4];
        float2 wv = *(const float2*)&Ws[k * K5PAD + tc * 2];
        a00 += xv.x * wv.x; a01 += xv.x * wv.y;
        a10 += xv.y * wv.x; a11 += xv.y * wv.y;
        a20 += xv.z * wv.x; a21 += xv.z * wv.y;
        a30 += xv.w * wv.x; a31 += xv.w * wv.y;
    }

    // ---- epilogue: exp, store, deterministic row partials ----
    int cA = c0 + tc * 2, cB = cA + 1;
    bool vA = cA < CC, vB = cB < CC;
    float racc[4];
    float accs[4][2] = {{a00, a01}, {a10, a11}, {a20, a21}, {a30, a31}};
#pragma unroll
    for (int i = 0; i < 4; i++) {
        int b = tbq * 4 + i;
        float e0 = vA ? __expf(accs[i][0]) : 0.f;
        float e1 = vB ? __expf(accs[i][1]) : 0.f;
        if (vA) g_logits[(size_t)b * CC + cA] = e0;
        if (vB) g_logits[(size_t)b * CC + cB] = e1;
        racc[i] = e0 + e1;
    }
#pragma unroll
    for (int i = 0; i < 4; i++)
        rpart[tc * 65 + tbq * 4 + i] = racc[i];
    __syncthreads();
    if (tid < BB) {
        float s = 0.f;
#pragma unroll
        for (int t2 = 0; t2 < 32; t2++) s += rpart[t2 * 65 + tid];
        g_psum[(size_t)tid * BLK5 + blockIdx.x] = s;
    }
}

// ---------------- kernel 6: scale exp by 1/rowsum ----------------
__global__ void k6_scale(float* __restrict__ out) {
    int b = blockIdx.x, ch = blockIdx.y, t = threadIdx.x;
    __shared__ float sred[8];
    float p = (t < BLK5) ? g_psum[(size_t)b * BLK5 + t] : 0.f;
#pragma unroll
    for (int off = 16; off; off >>= 1)
        p += __shfl_xor_sync(0xffffffffu, p, off);
    if ((t & 31) == 0) sred[t >> 5] = p;
    __syncthreads();
    float tot = ((sred[0] + sred[1]) + (sred[2] + sred[3])) +
                ((sred[4] + sred[5]) + (sred[6] + sred[7]));
    float inv = 1.0f / tot;

    int i = ch * 250 + t;
    if (t < 250) {
        float4 v = ((const float4*)(g_logits + (size_t)b * CC))[i];
        float4 r;
        r.x = v.x * inv; r.y = v.y * inv; r.z = v.z * inv; r.w = v.w * inv;
        ((float4*)(out + (size_t)b * CC))[i] = r;
    }
}

// ---------------- launch ----------------
extern "C" void kernel_launch(void* const* d_in, const int* in_sizes, int n_in,
                              void* d_out, int out_size) {
    const float* stories = (const float*)d_in[0];
    const float* queries = (const float*)d_in[1];
    const float* W1 = (const float*)d_in[2];
    const float* W2 = (const float*)d_in[3];
    const float* W3 = (const float*)d_in[4];
    const float* W4 = (const float*)d_in[5];
    float* out = (float*)d_out;

    static int k5_smem = 0;
    int smem5 = (2 * 128 * K5PAD + 32 * 65) * 4;
    if (!k5_smem) {
        cudaFuncSetAttribute(k5_logits,
                             cudaFuncAttributeMaxDynamicSharedMemorySize, smem5);
        k5_smem = 1;
    }

    k1_reduce_stories<<<BB * MSPLIT + PREF, 256>>>(stories, queries, W1, W2, W3);
    dim3 g3(NSPLIT, 2, 2);
    k3_gemm64<<<g3, 256>>>(queries, W1, W2, W4);
    k4_hops<<<BB, EE>>>(W3);
    k5_logits<<<BLK5, 512, smem5>>>(W4);
    dim3 g6(BB, 10);
    k6_scale<<<g6, 256>>>(out);
}

// round 5
// speedup vs baseline: 1.0662x; 1.0662x over previous
#include <cuda_runtime.h>
#include <math.h>

#define BB 64
#define MM 512
#define SS 1024
#define EE 128
#define CC 10000
#define MSPLIT 8
#define NSPLIT 32
#define KCHUNK (SS / NSPLIT)  /* 32 */
#define BLK5 ((CC + 63) / 64) /* 157 */
#define PREF 8

// ---------------- scratch (device globals; no allocation) ----------------
__device__ __align__(16) float g_partial[BB * MSPLIT * SS];   // 2 MB
__device__ __align__(16) float g_gpart[2 * NSPLIT * BB * EE]; // 2 MB
__device__ __align__(16) float g_u[BB * EE];                  // 32 KB
__device__ __align__(16) float g_logits[BB * CC];             // 2.56 MB (exp(logits))
__device__ __align__(16) float g_psum[BB * BLK5];
__device__ __align__(16) float g_dummy[128 * 256];

// ---------------- kernel 1: reduce stories over M + prefetch weights ------------
__global__ void k1_reduce_stories(const float* __restrict__ stories,
                                  const float* __restrict__ queries,
                                  const float* __restrict__ W1,
                                  const float* __restrict__ W2,
                                  const float* __restrict__ W3) {
    int blk = blockIdx.x;
    int t = threadIdx.x;

    if (blk >= BB * MSPLIT) {  // ---- L2 prefetch blocks ----
        int lane = (blk - BB * MSPLIT) * 256 + t;
        float s = 0.f;
        const float4* a = (const float4*)W1;
        for (int i = lane; i < 32768; i += PREF * 256) {
            float4 v = __ldcg(&a[i]); s += v.x + v.y + v.z + v.w;
        }
        a = (const float4*)W2;
        for (int i = lane; i < 32768; i += PREF * 256) {
            float4 v = __ldcg(&a[i]); s += v.x + v.y + v.z + v.w;
        }
        a = (const float4*)queries;
        for (int i = lane; i < 16384; i += PREF * 256) {
            float4 v = __ldcg(&a[i]); s += v.x + v.y + v.z + v.w;
        }
        a = (const float4*)W3;
        for (int i = lane; i < 4096; i += PREF * 256) {
            float4 v = __ldcg(&a[i]); s += v.x + v.y + v.z + v.w;
        }
        g_dummy[lane] = s;
        return;
    }

    int b = blk / MSPLIT, ms = blk % MSPLIT;
    const float4* src =
        (const float4*)(stories + (size_t)(b * MM + ms * (MM / MSPLIT)) * SS);
    float4 a0 = make_float4(0.f, 0.f, 0.f, 0.f);
    float4 a1 = a0, a2 = a0, a3 = a0;
#pragma unroll 4
    for (int m = 0; m < MM / MSPLIT; m += 4) {
        float4 v0 = __ldcs(&src[(size_t)(m + 0) * (SS / 4) + t]);
        float4 v1 = __ldcs(&src[(size_t)(m + 1) * (SS / 4) + t]);
        float4 v2 = __ldcs(&src[(size_t)(m + 2) * (SS / 4) + t]);
        float4 v3 = __ldcs(&src[(size_t)(m + 3) * (SS / 4) + t]);
        a0.x += v0.x; a0.y += v0.y; a0.z += v0.z; a0.w += v0.w;
        a1.x += v1.x; a1.y += v1.y; a1.z += v1.z; a1.w += v1.w;
        a2.x += v2.x; a2.y += v2.y; a2.z += v2.z; a2.w += v2.w;
        a3.x += v3.x; a3.y += v3.y; a3.z += v3.z; a3.w += v3.w;
    }
    float4 r;
    r.x = (a0.x + a1.x) + (a2.x + a3.x);
    r.y = (a0.y + a1.y) + (a2.y + a3.y);
    r.z = (a0.z + a1.z) + (a2.z + a3.z);
    r.w = (a0.w + a1.w) + (a2.w + a3.w);
    ((float4*)g_partial)[(size_t)blk * (SS / 4) + t] = r;
}

// ---------------- kernel 3: u0 = queries@W1^T, o = ssum@W2^T (split-K x32) ------
__global__ void k3_gemm64(const float* __restrict__ queries,
                          const float* __restrict__ W1,
                          const float* __restrict__ W2,
                          const float* __restrict__ W4) {
    int ks = blockIdx.x;
    int eh = blockIdx.y;
    int which = blockIdx.z;
    const float* W = which ? W2 : W1;
    int kbase = ks * KCHUNK;

    // W4 L2 prefetch for k5 across 128 blocks
    int bid = ks + NSPLIT * eh + NSPLIT * 2 * which;  // 0..127
    int plane = bid * 256 + threadIdx.x;
    float ps = 0.f;
    const float4* w4 = (const float4*)W4;
    for (int i = plane; i < 320000; i += 128 * 256) {
        float4 v = __ldcg(&w4[i]); ps += v.x + v.y + v.z + v.w;
    }

    __shared__ __align__(16) float Xs[32][68];
    __shared__ __align__(16) float Ws[32][68];

    int tid = threadIdx.x;
    int tb = tid & 15, te = tid >> 4;
    int lrow = tid >> 3, lkq = tid & 7;

    float acc[16];
#pragma unroll
    for (int i = 0; i < 16; i++) acc[i] = 0.f;

    {
#pragma unroll
        for (int h = 0; h < 2; h++) {
            int row = lrow + 32 * h;
            float4 xv;
            if (which == 0) {
                xv = *(const float4*)&queries[(size_t)row * SS + kbase + lkq * 4];
            } else {
                xv = make_float4(0.f, 0.f, 0.f, 0.f);
#pragma unroll
                for (int msp = 0; msp < MSPLIT; msp++) {
                    float4 v = *(const float4*)&g_partial[
                        (size_t)(row * MSPLIT + msp) * SS + kbase + lkq * 4];
                    xv.x += v.x; xv.y += v.y; xv.z += v.z; xv.w += v.w;
                }
            }
            float4 wv = *(const float4*)&W[(size_t)(eh * 64 + row) * SS + kbase + lkq * 4];
            Xs[lkq * 4 + 0][row] = xv.x; Xs[lkq * 4 + 1][row] = xv.y;
            Xs[lkq * 4 + 2][row] = xv.z; Xs[lkq * 4 + 3][row] = xv.w;
            Ws[lkq * 4 + 0][row] = wv.x; Ws[lkq * 4 + 1][row] = wv.y;
            Ws[lkq * 4 + 2][row] = wv.z; Ws[lkq * 4 + 3][row] = wv.w;
        }
        __syncthreads();
#pragma unroll
        for (int k = 0; k < 32; k++) {
            float4 xv = *(const float4*)&Xs[k][tb * 4];
            float4 wv = *(const float4*)&Ws[k][te * 4];
            acc[0]  += xv.x * wv.x; acc[1]  += xv.x * wv.y;
            acc[2]  += xv.x * wv.z; acc[3]  += xv.x * wv.w;
            acc[4]  += xv.y * wv.x; acc[5]  += xv.y * wv.y;
            acc[6]  += xv.y * wv.z; acc[7]  += xv.y * wv.w;
            acc[8]  += xv.z * wv.x; acc[9]  += xv.z * wv.y;
            acc[10] += xv.z * wv.z; acc[11] += xv.z * wv.w;
            acc[12] += xv.w * wv.x; acc[13] += xv.w * wv.y;
            acc[14] += xv.w * wv.z; acc[15] += xv.w * wv.w;
        }
    }
#pragma unroll
    for (int i = 0; i < 4; i++)
#pragma unroll
        for (int j = 0; j < 4; j++)
            g_gpart[(size_t)((which * NSPLIT + ks) * BB + tb * 4 + i) * EE +
                    eh * 64 + te * 4 + j] = acc[i * 4 + j];
    g_dummy[plane] = ps;
}

// ---------------- kernel 4: split-K combine + 3 hops + L2 normalize -------------
__global__ void k4_hops(const float* __restrict__ W3) {
    __shared__ float us[EE];
    __shared__ float red[4];
    int b = blockIdx.x;
    int f = threadIdx.x;

    float4 w[32];
    const float4* wrow = (const float4*)(W3 + (size_t)f * EE);
#pragma unroll
    for (int q = 0; q < 32; q++) w[q] = __ldcg(&wrow[q]);

    float u = 0.f, o = 0.f;
#pragma unroll
    for (int ks = 0; ks < NSPLIT; ks++) {
        u += g_gpart[(size_t)(ks * BB + b) * EE + f];
        o += g_gpart[(size_t)((NSPLIT + ks) * BB + b) * EE + f];
    }
    us[f] = u;
    __syncthreads();

    float vout = 0.f;
    const float4* us4 = (const float4*)us;
    for (int hop = 0; hop < 3; hop++) {
        float v0 = 0.f, v1 = 0.f, v2 = 0.f, v3 = 0.f;
#pragma unroll
        for (int q = 0; q < 32; q++) {
            float4 uu = us4[q];
            v0 += w[q].x * uu.x;
            v1 += w[q].y * uu.y;
            v2 += w[q].z * uu.z;
            v3 += w[q].w * uu.w;
        }
        float v = o + ((v0 + v1) + (v2 + v3));
        float s = v * v;
#pragma unroll
        for (int off = 16; off; off >>= 1)
            s += __shfl_xor_sync(0xffffffffu, s, off);
        if ((f & 31) == 0) red[f >> 5] = s;
        __syncthreads();
        float tot = (red[0] + red[1]) + (red[2] + red[3]);
        float nrm = fmaxf(sqrtf(tot), 1e-12f);
        vout = v / nrm;
        us[f] = vout;
        __syncthreads();
    }
    g_u[(size_t)b * EE + f] = vout;
}

// ---------------- kernel 5: exp(u @ W4^T) — pipelined, high-reg, barrier-free ---
// grid = 157, block = 512, __launch_bounds__(512,1) -> reg cap 128.
// K staged fully in shared ([132 rows][68] pitch so the 2-deep pipeline can
// over-read rows 128..131 harmlessly). Thread tile 4b x 2c; Xs read is a warp
// broadcast, Ws read is 2 wavefronts. Explicit double-buffered inner loop.
#define K5PAD 68
#define K5ROWS 132
__global__ void __launch_bounds__(512, 1) k5_logits(const float* __restrict__ W4) {
    extern __shared__ float sm[];
    float* Xs = sm;                         // [K5ROWS][K5PAD]
    float* Ws = sm + K5ROWS * K5PAD;        // [K5ROWS][K5PAD]
    float* rpart = sm + 2 * K5ROWS * K5PAD; // [32][65]

    int c0 = blockIdx.x * 64;
    int tid = threadIdx.x;
    int tc = tid & 31;       // column pair: cols tc*2, tc*2+1
    int tbq = tid >> 5;      // warp id 0..15: rows tbq*4 .. +3

    // ---- load phase: transpose g_u and W4 tile into [k][row] layout ----
    {
        int r = tid & 63;
        int qb = tid >> 6;   // 0..7
        const float4* usrc = (const float4*)(g_u + (size_t)r * EE);
        int crow = c0 + r;
        const float4* wsrc = (const float4*)(W4 + (size_t)crow * EE);
#pragma unroll
        for (int j = 0; j < 4; j++) {
            int q = qb + 8 * j;
            float4 xv = usrc[q];
            Xs[(4 * q + 0) * K5PAD + r] = xv.x;
            Xs[(4 * q + 1) * K5PAD + r] = xv.y;
            Xs[(4 * q + 2) * K5PAD + r] = xv.z;
            Xs[(4 * q + 3) * K5PAD + r] = xv.w;
            float4 wv = make_float4(0.f, 0.f, 0.f, 0.f);
            if (crow < CC) wv = wsrc[q];
            Ws[(4 * q + 0) * K5PAD + r] = wv.x;
            Ws[(4 * q + 1) * K5PAD + r] = wv.y;
            Ws[(4 * q + 2) * K5PAD + r] = wv.z;
            Ws[(4 * q + 3) * K5PAD + r] = wv.w;
        }
    }
    __syncthreads();

    // ---- compute: software-pipelined, no barriers ----
    const float* xbase = Xs + tbq * 4;
    const float* wbase = Ws + tc * 2;

    float a00 = 0.f, a01 = 0.f, a10 = 0.f, a11 = 0.f;
    float a20 = 0.f, a21 = 0.f, a30 = 0.f, a31 = 0.f;

    float4 xa = *(const float4*)(xbase);
    float2 wa = *(const float2*)(wbase);
    float4 xb = *(const float4*)(xbase + K5PAD);
    float2 wb = *(const float2*)(wbase + K5PAD);

#pragma unroll 8
    for (int k = 0; k < EE; k += 2) {
        float4 xc = *(const float4*)(xbase + (size_t)(k + 2) * K5PAD);
        float2 wc = *(const float2*)(wbase + (size_t)(k + 2) * K5PAD);
        a00 += xa.x * wa.x; a01 += xa.x * wa.y;
        a10 += xa.y * wa.x; a11 += xa.y * wa.y;
        a20 += xa.z * wa.x; a21 += xa.z * wa.y;
        a30 += xa.w * wa.x; a31 += xa.w * wa.y;
        float4 xd = *(const float4*)(xbase + (size_t)(k + 3) * K5PAD);
        float2 wd = *(const float2*)(wbase + (size_t)(k + 3) * K5PAD);
        a00 += xb.x * wb.x; a01 += xb.x * wb.y;
        a10 += xb.y * wb.x; a11 += xb.y * wb.y;
        a20 += xb.z * wb.x; a21 += xb.z * wb.y;
        a30 += xb.w * wb.x; a31 += xb.w * wb.y;
        xa = xc; wa = wc;
        xb = xd; wb = wd;
    }

    // ---- epilogue: exp, store, deterministic row partials ----
    int cA = c0 + tc * 2, cB = cA + 1;
    bool vA = cA < CC, vB = cB < CC;
    float e00 = vA ? __expf(a00) : 0.f, e01 = vB ? __expf(a01) : 0.f;
    float e10 = vA ? __expf(a10) : 0.f, e11 = vB ? __expf(a11) : 0.f;
    float e20 = vA ? __expf(a20) : 0.f, e21 = vB ? __expf(a21) : 0.f;
    float e30 = vA ? __expf(a30) : 0.f, e31 = vB ? __expf(a31) : 0.f;
    int b0 = tbq * 4;
    if (vA) {
        g_logits[(size_t)(b0 + 0) * CC + cA] = e00;
        g_logits[(size_t)(b0 + 1) * CC + cA] = e10;
        g_logits[(size_t)(b0 + 2) * CC + cA] = e20;
        g_logits[(size_t)(b0 + 3) * CC + cA] = e30;
    }
    if (vB) {
        g_logits[(size_t)(b0 + 0) * CC + cB] = e01;
        g_logits[(size_t)(b0 + 1) * CC + cB] = e11;
        g_logits[(size_t)(b0 + 2) * CC + cB] = e21;
        g_logits[(size_t)(b0 + 3) * CC + cB] = e31;
    }
    rpart[tc * 65 + b0 + 0] = e00 + e01;
    rpart[tc * 65 + b0 + 1] = e10 + e11;
    rpart[tc * 65 + b0 + 2] = e20 + e21;
    rpart[tc * 65 + b0 + 3] = e30 + e31;
    __syncthreads();
    if (tid < BB) {
        float s = 0.f;
#pragma unroll
        for (int t2 = 0; t2 < 32; t2++) s += rpart[t2 * 65 + tid];
        g_psum[(size_t)tid * BLK5 + blockIdx.x] = s;
    }
}

// ---------------- kernel 6: scale exp by 1/rowsum ----------------
__global__ void k6_scale(float* __restrict__ out) {
    int b = blockIdx.x, ch = blockIdx.y, t = threadIdx.x;
    __shared__ float sred[8];
    float p = (t < BLK5) ? g_psum[(size_t)b * BLK5 + t] : 0.f;
#pragma unroll
    for (int off = 16; off; off >>= 1)
        p += __shfl_xor_sync(0xffffffffu, p, off);
    if ((t & 31) == 0) sred[t >> 5] = p;
    __syncthreads();
    float tot = ((sred[0] + sred[1]) + (sred[2] + sred[3])) +
                ((sred[4] + sred[5]) + (sred[6] + sred[7]));
    float inv = 1.0f / tot;

    int i = ch * 250 + t;
    if (t < 250) {
        float4 v = ((const float4*)(g_logits + (size_t)b * CC))[i];
        float4 r;
        r.x = v.x * inv; r.y = v.y * inv; r.z = v.z * inv; r.w = v.w * inv;
        ((float4*)(out + (size_t)b * CC))[i] = r;
    }
}

// ---------------- launch ----------------
extern "C" void kernel_launch(void* const* d_in, const int* in_sizes, int n_in,
                              void* d_out, int out_size) {
    const float* stories = (const float*)d_in[0];
    const float* queries = (const float*)d_in[1];
    const float* W1 = (const float*)d_in[2];
    const float* W2 = (const float*)d_in[3];
    const float* W3 = (const float*)d_in[4];
    const float* W4 = (const float*)d_in[5];
    float* out = (float*)d_out;

    static int k5_smem = 0;
    int smem5 = (2 * K5ROWS * K5PAD + 32 * 65) * 4;
    if (!k5_smem) {
        cudaFuncSetAttribute(k5_logits,
                             cudaFuncAttributeMaxDynamicSharedMemorySize, smem5);
        k5_smem = 1;
    }

    k1_reduce_stories<<<BB * MSPLIT + PREF, 256>>>(stories, queries, W1, W2, W3);
    dim3 g3(NSPLIT, 2, 2);
    k3_gemm64<<<g3, 256>>>(queries, W1, W2, W4);
    k4_hops<<<BB, EE>>>(W3);
    k5_logits<<<BLK5, 512, smem5>>>(W4);
    dim3 g6(BB, 10);
    k6_scale<<<g6, 256>>>(out);
}